// round 3
// baseline (speedup 1.0000x reference)
#include <cuda_runtime.h>
#include <math.h>

#define BATCH 512
#define INDIM 256
#define HIDD  512
#define HID2  256
#define PAT   10

typedef unsigned long long u64;

// -------- scratch (no allocations allowed) --------
__device__ float g_H [BATCH * HIDD];
__device__ float g_H2[BATCH * HID2];
__device__ float g_A [BATCH * HIDD];
__device__ float g_C [BATCH * HIDD];

// ---------- packed f32x2 helpers (sm_103a) ----------
__device__ __forceinline__ u64 pack2(float lo, float hi) {
    u64 r; asm("mov.b64 %0, {%1, %2};" : "=l"(r) : "f"(lo), "f"(hi)); return r;
}
__device__ __forceinline__ void unpack2(u64 v, float& lo, float& hi) {
    asm("mov.b64 {%0, %1}, %2;" : "=f"(lo), "=f"(hi) : "l"(v));
}
__device__ __forceinline__ u64 ffma2(u64 a, u64 b, u64 c) {
    u64 d; asm("fma.rn.f32x2 %0, %1, %2, %3;" : "=l"(d) : "l"(a), "l"(b), "l"(c)); return d;
}
__device__ __forceinline__ u64 dup2(float v) { return pack2(v, v); }

// ============================================================
// Split-K GEMM tile: Out[m][n] = sum_k X[m][k]*W[n][k] (+epilogue)
// 512 threads = 4 warpgroups, each wg computes the full 64x64 tile
// over its K/4 slice; partials combined via smem in 3 rounds.
// Per wg: 128 thr as 16(m-groups of 4) x 8(n-groups of 8), 4x8 microtile,
// f32x2 FMA (n packed in pairs). Single-buffered smem, 16-deep K chunks.
// smem: per-wg bufs 2048 floats (Xs 16x64, Wt 16x64) at sm[wg*2048],
//       exchange 4096 floats at sm[8192]. Total 12288 floats = 48KB.
// mode 0: BN(+b1)+ReLU ; 1: none ; 2: +p0 ; 3: relu(+p0)
// ============================================================
__device__ __forceinline__ void gemm_sk(
    const float* __restrict__ X, const float* __restrict__ W,
    float* __restrict__ Out, int N, int K, int m0, int n0, int mode,
    const float* __restrict__ p0, const float* __restrict__ p1,
    const float* __restrict__ p2, const float* __restrict__ p3,
    const float* __restrict__ p4, float* sm)
{
    const int tid = threadIdx.x;
    const int wg  = tid >> 7;
    const int t   = tid & 127;
    const int Kq  = K >> 2;
    const int kb  = wg * Kq;

    float* Xs = sm + wg * 2048;   // [16][64] k-major, m contiguous
    float* Wt = Xs + 1024;        // [16][64] k-major, n contiguous
    float* ex = sm + 8192;        // 4096 floats

    const int txn = t & 7;        // 8 n cols (n0 + txn*8)
    const int tym = t >> 3;       // 16 m quads (m0 + tym*4)

    const int lr  = t & 63;       // loader row
    const int lkh = (t >> 6) * 8; // k offset 0 or 8 within chunk

    const float* Xg = X + (size_t)(m0 + lr) * K + kb + lkh;
    const float* Wg = W + (size_t)(n0 + lr) * K + kb + lkh;

    u64 acc[4][4];
#pragma unroll
    for (int r = 0; r < 4; r++)
#pragma unroll
        for (int c = 0; c < 4; c++) acc[r][c] = 0ull;

    const int NC = Kq >> 4;

    float4 xa = *(const float4*)(Xg);
    float4 xb = *(const float4*)(Xg + 4);
    float4 wa = *(const float4*)(Wg);
    float4 wb = *(const float4*)(Wg + 4);

#pragma unroll 1
    for (int c = 0; c < NC; ++c) {
        // store chunk c registers -> smem
        Xs[(lkh + 0) * 64 + lr] = xa.x; Xs[(lkh + 1) * 64 + lr] = xa.y;
        Xs[(lkh + 2) * 64 + lr] = xa.z; Xs[(lkh + 3) * 64 + lr] = xa.w;
        Xs[(lkh + 4) * 64 + lr] = xb.x; Xs[(lkh + 5) * 64 + lr] = xb.y;
        Xs[(lkh + 6) * 64 + lr] = xb.z; Xs[(lkh + 7) * 64 + lr] = xb.w;
        Wt[(lkh + 0) * 64 + lr] = wa.x; Wt[(lkh + 1) * 64 + lr] = wa.y;
        Wt[(lkh + 2) * 64 + lr] = wa.z; Wt[(lkh + 3) * 64 + lr] = wa.w;
        Wt[(lkh + 4) * 64 + lr] = wb.x; Wt[(lkh + 5) * 64 + lr] = wb.y;
        Wt[(lkh + 6) * 64 + lr] = wb.z; Wt[(lkh + 7) * 64 + lr] = wb.w;
        __syncthreads();

        if (c + 1 < NC) {
            const int ko = (c + 1) * 16;
            xa = *(const float4*)(Xg + ko);
            xb = *(const float4*)(Xg + ko + 4);
            wa = *(const float4*)(Wg + ko);
            wb = *(const float4*)(Wg + ko + 4);
        }

#pragma unroll
        for (int kk = 0; kk < 16; kk++) {
            float4 a = *(const float4*)&Xs[kk * 64 + tym * 4];
            ulonglong2 b0 = *(const ulonglong2*)&Wt[kk * 64 + txn * 8];
            ulonglong2 b1 = *(const ulonglong2*)&Wt[kk * 64 + txn * 8 + 4];
            u64 a0 = dup2(a.x), a1 = dup2(a.y), a2 = dup2(a.z), a3 = dup2(a.w);
            acc[0][0] = ffma2(a0, b0.x, acc[0][0]); acc[0][1] = ffma2(a0, b0.y, acc[0][1]);
            acc[0][2] = ffma2(a0, b1.x, acc[0][2]); acc[0][3] = ffma2(a0, b1.y, acc[0][3]);
            acc[1][0] = ffma2(a1, b0.x, acc[1][0]); acc[1][1] = ffma2(a1, b0.y, acc[1][1]);
            acc[1][2] = ffma2(a1, b1.x, acc[1][2]); acc[1][3] = ffma2(a1, b1.y, acc[1][3]);
            acc[2][0] = ffma2(a2, b0.x, acc[2][0]); acc[2][1] = ffma2(a2, b0.y, acc[2][1]);
            acc[2][2] = ffma2(a2, b1.x, acc[2][2]); acc[2][3] = ffma2(a2, b1.y, acc[2][3]);
            acc[3][0] = ffma2(a3, b0.x, acc[3][0]); acc[3][1] = ffma2(a3, b0.y, acc[3][1]);
            acc[3][2] = ffma2(a3, b1.x, acc[3][2]); acc[3][3] = ffma2(a3, b1.y, acc[3][3]);
        }
        __syncthreads();
    }

    // ---- combine partials: wg0 accumulates wg1..3 via ex ----
    float va[4][8];
    if (wg == 0) {
#pragma unroll
        for (int r = 0; r < 4; r++) {
            unpack2(acc[r][0], va[r][0], va[r][1]);
            unpack2(acc[r][1], va[r][2], va[r][3]);
            unpack2(acc[r][2], va[r][4], va[r][5]);
            unpack2(acc[r][3], va[r][6], va[r][7]);
        }
    }
#pragma unroll 1
    for (int s = 1; s < 4; ++s) {
        if (wg == s) {
#pragma unroll
            for (int r = 0; r < 4; r++) {
                float v[8];
                unpack2(acc[r][0], v[0], v[1]);
                unpack2(acc[r][1], v[2], v[3]);
                unpack2(acc[r][2], v[4], v[5]);
                unpack2(acc[r][3], v[6], v[7]);
                *(float4*)&ex[(tym * 4 + r) * 64 + txn * 8] =
                    make_float4(v[0], v[1], v[2], v[3]);
                *(float4*)&ex[(tym * 4 + r) * 64 + txn * 8 + 4] =
                    make_float4(v[4], v[5], v[6], v[7]);
            }
        }
        __syncthreads();
        if (wg == 0) {
#pragma unroll
            for (int r = 0; r < 4; r++) {
                float4 e0 = *(const float4*)&ex[(tym * 4 + r) * 64 + txn * 8];
                float4 e1 = *(const float4*)&ex[(tym * 4 + r) * 64 + txn * 8 + 4];
                va[r][0] += e0.x; va[r][1] += e0.y; va[r][2] += e0.z; va[r][3] += e0.w;
                va[r][4] += e1.x; va[r][5] += e1.y; va[r][6] += e1.z; va[r][7] += e1.w;
            }
        }
        __syncthreads();
    }

    if (wg != 0) return;

    // ---- epilogue ----
    const int n = n0 + txn * 8;
#pragma unroll
    for (int r = 0; r < 4; r++) {
        float v[8];
#pragma unroll
        for (int c2 = 0; c2 < 8; c2++) {
            float v2 = va[r][c2];
            if (mode == 0) {
                v2 += p0[n + c2];
                v2 = p1[n + c2] * (v2 - p3[n + c2]) * rsqrtf(p4[n + c2] + 1e-5f)
                     + p2[n + c2];
                v2 = fmaxf(v2, 0.f);
            } else if (mode == 2) {
                v2 += p0[n + c2];
            } else if (mode == 3) {
                v2 = fmaxf(v2 + p0[n + c2], 0.f);
            }
            v[c2] = v2;
        }
        float* o = Out + (size_t)(m0 + tym * 4 + r) * N + n;
        *(float4*)o       = make_float4(v[0], v[1], v[2], v[3]);
        *(float4*)(o + 4) = make_float4(v[4], v[5], v[6], v[7]);
    }
}

// ============================================================
// Launch 1: three fused x-projections (H via BN+ReLU, A, C+bs1)
// grid (8 n-tiles, 8 m-tiles, 3 weights), 512 threads.
// ============================================================
__global__ __launch_bounds__(512)
void k_proj(const float* __restrict__ x,
            const float* __restrict__ W1, const float* __restrict__ b1,
            const float* __restrict__ gam, const float* __restrict__ bet,
            const float* __restrict__ mean, const float* __restrict__ var,
            const float* __restrict__ Wa, const float* __restrict__ Wb,
            const float* __restrict__ bs1)
{
    __shared__ __align__(16) float sm[12288];
    const int m0 = blockIdx.y * 64;
    const int n0 = blockIdx.x * 64;
    const int z  = blockIdx.z;
    if (z == 0)
        gemm_sk(x, W1, g_H, HIDD, INDIM, m0, n0, 0, b1, gam, bet, mean, var, sm);
    else if (z == 1)
        gemm_sk(x, Wa, g_A, HIDD, INDIM, m0, n0, 1,
                nullptr, nullptr, nullptr, nullptr, nullptr, sm);
    else
        gemm_sk(x, Wb, g_C, HIDD, INDIM, m0, n0, 2,
                bs1, nullptr, nullptr, nullptr, nullptr, sm);
}

// ============================================================
// Launch 2: blocks [0,136) = similarity tiles (upper triangle),
//           blocks [136,168) = H2 = relu(H @ W2^T + b2) 64x64 tiles.
// 512 threads; sim also uses 4-way split-K (K quarter = 128).
// sim tile 32i x 32j, per wg: 16x8 thread grid, 2i x 4j microtile.
// ============================================================
__global__ __launch_bounds__(512)
void k_simh2(const float* __restrict__ W2, const float* __restrict__ b2,
             const float* __restrict__ ws2, const float* __restrict__ bs2p,
             float* __restrict__ out_sim)
{
    __shared__ __align__(16) float sm[12288];

    if (blockIdx.x >= 136) {
        const int idx = blockIdx.x - 136;        // 0..31
        const int m0 = (idx >> 2) * 64;          // 8 m-tiles
        const int n0 = (idx & 3) * 64;           // 4 n-tiles
        gemm_sk(g_H, W2, g_H2, HID2, HIDD, m0, n0, 3,
                b2, nullptr, nullptr, nullptr, nullptr, sm);
        return;
    }

    // ---- similarity tile ----
    const int tid = threadIdx.x;
    const int wg  = tid >> 7;
    const int t   = tid & 127;

    float* As = sm + wg * 2080;   // [32][32] k-major
    float* Cs = As + 1024;
    float* Ws = As + 2048;        // 32 floats
    float* ex = sm + 4 * 2080;    // 1024 floats

    // decode upper-triangle tile (bi <= bj)
    int rb = blockIdx.x, bi = 0;
    while (rb >= 16 - bi) { rb -= 16 - bi; ++bi; }
    const int bj = bi + rb;
    const int i0 = bi * 32, j0 = bj * 32;

    const int tx = t & 7;     // 4 j cols
    const int ty = t >> 3;    // 2 i rows

    const int lrow = t & 31;
    const int lkh  = (t >> 5) * 8;   // 0,8,16,24
    const int kb   = wg * 128;

    const float* Ag = g_A + (size_t)(i0 + lrow) * HIDD + kb + lkh;
    const float* Cg = g_C + (size_t)(j0 + lrow) * HIDD + kb + lkh;
    const float* Wg = ws2 + kb;

    float acc[2][4];
#pragma unroll
    for (int r = 0; r < 2; r++)
#pragma unroll
        for (int c = 0; c < 4; c++) acc[r][c] = 0.f;

    float4 aa = *(const float4*)(Ag);
    float4 ab = *(const float4*)(Ag + 4);
    float4 ca = *(const float4*)(Cg);
    float4 cb = *(const float4*)(Cg + 4);
    float4 wv;
    if (t < 8) wv = *(const float4*)(Wg + t * 4);

#pragma unroll 1
    for (int c = 0; c < 4; ++c) {            // 4 chunks of 32 k
        As[(lkh + 0) * 32 + lrow] = aa.x; As[(lkh + 1) * 32 + lrow] = aa.y;
        As[(lkh + 2) * 32 + lrow] = aa.z; As[(lkh + 3) * 32 + lrow] = aa.w;
        As[(lkh + 4) * 32 + lrow] = ab.x; As[(lkh + 5) * 32 + lrow] = ab.y;
        As[(lkh + 6) * 32 + lrow] = ab.z; As[(lkh + 7) * 32 + lrow] = ab.w;
        Cs[(lkh + 0) * 32 + lrow] = ca.x; Cs[(lkh + 1) * 32 + lrow] = ca.y;
        Cs[(lkh + 2) * 32 + lrow] = ca.z; Cs[(lkh + 3) * 32 + lrow] = ca.w;
        Cs[(lkh + 4) * 32 + lrow] = cb.x; Cs[(lkh + 5) * 32 + lrow] = cb.y;
        Cs[(lkh + 6) * 32 + lrow] = cb.z; Cs[(lkh + 7) * 32 + lrow] = cb.w;
        if (t < 8) *(float4*)&Ws[t * 4] = wv;
        __syncthreads();

        if (c + 1 < 4) {
            const int ko = (c + 1) * 32;
            aa = *(const float4*)(Ag + ko);
            ab = *(const float4*)(Ag + ko + 4);
            ca = *(const float4*)(Cg + ko);
            cb = *(const float4*)(Cg + ko + 4);
            if (t < 8) wv = *(const float4*)(Wg + ko + t * 4);
        }

#pragma unroll
        for (int kk = 0; kk < 32; kk++) {
            float2 a  = *(const float2*)&As[kk * 32 + ty * 2];
            float4 cc = *(const float4*)&Cs[kk * 32 + tx * 4];
            const float w = Ws[kk];
            acc[0][0] += fmaxf(a.x + cc.x, 0.f) * w;
            acc[0][1] += fmaxf(a.x + cc.y, 0.f) * w;
            acc[0][2] += fmaxf(a.x + cc.z, 0.f) * w;
            acc[0][3] += fmaxf(a.x + cc.w, 0.f) * w;
            acc[1][0] += fmaxf(a.y + cc.x, 0.f) * w;
            acc[1][1] += fmaxf(a.y + cc.y, 0.f) * w;
            acc[1][2] += fmaxf(a.y + cc.z, 0.f) * w;
            acc[1][3] += fmaxf(a.y + cc.w, 0.f) * w;
        }
        __syncthreads();
    }

    // ---- combine partials ----
#pragma unroll 1
    for (int s = 1; s < 4; ++s) {
        if (wg == s) {
            *(float4*)&ex[t * 8]     = make_float4(acc[0][0], acc[0][1], acc[0][2], acc[0][3]);
            *(float4*)&ex[t * 8 + 4] = make_float4(acc[1][0], acc[1][1], acc[1][2], acc[1][3]);
        }
        __syncthreads();
        if (wg == 0) {
            float4 e0 = *(const float4*)&ex[t * 8];
            float4 e1 = *(const float4*)&ex[t * 8 + 4];
            acc[0][0] += e0.x; acc[0][1] += e0.y; acc[0][2] += e0.z; acc[0][3] += e0.w;
            acc[1][0] += e1.x; acc[1][1] += e1.y; acc[1][2] += e1.z; acc[1][3] += e1.w;
        }
        __syncthreads();
    }
    if (wg != 0) return;

    const float bs2 = *bs2p;
#pragma unroll
    for (int r = 0; r < 2; r++) {
#pragma unroll
        for (int c = 0; c < 4; c++) {
            const int i = i0 + ty * 2 + r;
            const int j = j0 + tx * 4 + c;
            if (i < j) {
                const float s = 1.f / (1.f + __expf(-(acc[r][c] + bs2)));
                out_sim[(size_t)i * BATCH + j] = s;
                out_sim[(size_t)j * BATCH + i] = s;
            } else if (i == j) {
                out_sim[(size_t)i * BATCH + j] = 0.f;
            }
        }
    }
}

// ============================================================
// Launch 3: scores + softmax (reads g_H2), one warp per row.
// ============================================================
__global__ __launch_bounds__(256)
void k_scores(const float* __restrict__ W3, const float* __restrict__ b3,
              float* __restrict__ out_probs, float* __restrict__ out_scores)
{
    const int warp = threadIdx.x >> 5;
    const int lane = threadIdx.x & 31;
    const int row  = blockIdx.x * 8 + warp;
    const float* h = g_H2 + (size_t)row * HID2;

    float acc[PAT];
#pragma unroll
    for (int p = 0; p < PAT; p++) acc[p] = 0.f;

    for (int k = lane; k < HID2; k += 32) {
        const float hv = h[k];
#pragma unroll
        for (int p = 0; p < PAT; p++) acc[p] += hv * W3[p * HID2 + k];
    }
#pragma unroll
    for (int p = 0; p < PAT; p++) {
#pragma unroll
        for (int off = 16; off; off >>= 1)
            acc[p] += __shfl_xor_sync(0xFFFFFFFFu, acc[p], off);
    }
    if (lane == 0) {
        float s[PAT], e[PAT];
        float mx = -1e30f;
#pragma unroll
        for (int p = 0; p < PAT; p++) { s[p] = acc[p] + b3[p]; mx = fmaxf(mx, s[p]); }
        float sum = 0.f;
#pragma unroll
        for (int p = 0; p < PAT; p++) { e[p] = __expf(s[p] - mx); sum += e[p]; }
        const float inv = 1.f / sum;
#pragma unroll
        for (int p = 0; p < PAT; p++) {
            out_scores[row * PAT + p] = s[p];
            out_probs [row * PAT + p] = e[p] * inv;
        }
    }
}

// ============================================================
extern "C" void kernel_launch(void* const* d_in, const int* in_sizes, int n_in,
                              void* d_out, int out_size)
{
    const float* x    = (const float*)d_in[0];
    const float* W1   = (const float*)d_in[1];
    const float* b1   = (const float*)d_in[2];
    const float* gam  = (const float*)d_in[3];
    const float* bet  = (const float*)d_in[4];
    const float* mean = (const float*)d_in[5];
    const float* var  = (const float*)d_in[6];
    const float* W2   = (const float*)d_in[7];
    const float* b2   = (const float*)d_in[8];
    const float* W3   = (const float*)d_in[9];
    const float* b3   = (const float*)d_in[10];
    const float* Wa   = (const float*)d_in[11];
    const float* Wb   = (const float*)d_in[12];
    const float* bs1  = (const float*)d_in[13];
    const float* ws2  = (const float*)d_in[14];
    const float* bs2  = (const float*)d_in[15];

    float* out        = (float*)d_out;
    float* out_probs  = out;
    float* out_scores = out + BATCH * PAT;
    float* out_sim    = out + 2 * BATCH * PAT;

    // 1) H, A, C projections (192 CTAs x 512 threads, 4-way split-K)
    k_proj<<<dim3(8, 8, 3), 512>>>(x, W1, b1, gam, bet, mean, var, Wa, Wb, bs1);
    // 2) sim (136 CTAs) + H2 (32 CTAs), 512 threads each
    k_simh2<<<168, 512>>>(W2, b2, ws2, bs2, out_sim);
    // 3) scores + softmax
    k_scores<<<64, 256>>>(W3, b3, out_probs, out_scores);
}

// round 4
// speedup vs baseline: 1.4786x; 1.4786x over previous
#include <cuda_runtime.h>
#include <math.h>

#define BATCH 512
#define INDIM 256
#define HIDD  512
#define HID2  256
#define PAT   10

typedef unsigned long long u64;

// -------- scratch (no allocations allowed) --------
__device__ float g_H [BATCH * HIDD];
__device__ float g_H2[BATCH * HID2];
__device__ float g_A [BATCH * HIDD];
__device__ float g_C [BATCH * HIDD];

// ---------- packed f32x2 helpers (sm_103a) ----------
__device__ __forceinline__ u64 pack2(float lo, float hi) {
    u64 r; asm("mov.b64 %0, {%1, %2};" : "=l"(r) : "f"(lo), "f"(hi)); return r;
}
__device__ __forceinline__ void unpack2(u64 v, float& lo, float& hi) {
    asm("mov.b64 {%0, %1}, %2;" : "=f"(lo), "=f"(hi) : "l"(v));
}
__device__ __forceinline__ u64 ffma2(u64 a, u64 b, u64 c) {
    u64 d; asm("fma.rn.f32x2 %0, %1, %2, %3;" : "=l"(d) : "l"(a), "l"(b), "l"(c)); return d;
}
__device__ __forceinline__ u64 dup2(float v) { return pack2(v, v); }

// ============================================================
// GEMM tile: Out[m][n] = sum_k X[m][k]*W[n][k]  (+epilogue)
// 64m x 32n tile, 128 threads, 4x4 micro-tile, f32x2 FMA,
// double-buffered smem (1 barrier per 16-deep K chunk),
// distance-1 register prefetch on the kk loop (LDS latency hiding).
// mode 0: BN(+b1)+ReLU ; 1: none ; 2: +p0 ; 3: relu(+p0)
// ============================================================
__device__ __forceinline__ void gemm_tile(
    const float* __restrict__ X, const float* __restrict__ W,
    float* __restrict__ Out, int N, int K, int m0, int n0, int mode,
    const float* __restrict__ p0, const float* __restrict__ p1,
    const float* __restrict__ p2, const float* __restrict__ p3,
    const float* __restrict__ p4, float* sm)
{
    float* Xs = sm;          // 2 * 16 * 64
    float* Wt = sm + 2048;   // 2 * 16 * 32

    const int t   = threadIdx.x;
    const int txn = t & 7;        // n quad (4 cols)
    const int tym = t >> 3;       // m quad (4 rows), 0..15

    const int xrow = t & 63;      // X loader row
    const int xkq  = t >> 6;      // 0..1 (handles kq and kq+2)
    const int wrow = t & 31;      // W loader row
    const int wkq  = t >> 5;      // 0..3

    const float* Xg = X + (size_t)(m0 + xrow) * K;
    const float* Wg = W + (size_t)(n0 + wrow) * K;

    // ---- load chunk 0 ----
    {
        float4 v0 = *(const float4*)(Xg + xkq * 4);
        float4 v1 = *(const float4*)(Xg + (xkq + 2) * 4);
        float4 wv = *(const float4*)(Wg + wkq * 4);
        Xs[(xkq*4+0)*64 + xrow] = v0.x; Xs[(xkq*4+1)*64 + xrow] = v0.y;
        Xs[(xkq*4+2)*64 + xrow] = v0.z; Xs[(xkq*4+3)*64 + xrow] = v0.w;
        Xs[((xkq+2)*4+0)*64 + xrow] = v1.x; Xs[((xkq+2)*4+1)*64 + xrow] = v1.y;
        Xs[((xkq+2)*4+2)*64 + xrow] = v1.z; Xs[((xkq+2)*4+3)*64 + xrow] = v1.w;
        Wt[(wkq*4+0)*32 + wrow] = wv.x; Wt[(wkq*4+1)*32 + wrow] = wv.y;
        Wt[(wkq*4+2)*32 + wrow] = wv.z; Wt[(wkq*4+3)*32 + wrow] = wv.w;
    }
    __syncthreads();

    u64 acc[4][2];
#pragma unroll
    for (int r = 0; r < 4; r++) { acc[r][0] = pack2(0.f, 0.f); acc[r][1] = acc[r][0]; }

    const int NC = K >> 4;
#pragma unroll 1
    for (int c = 0; c < NC; ++c) {
        const float* Xb = Xs + (c & 1) * 1024;
        const float* Wb = Wt + (c & 1) * 512;

        float4 v0, v1, wv;
        const bool pf = (c + 1 < NC);
        if (pf) {
            const int k0 = (c + 1) << 4;
            v0 = *(const float4*)(Xg + k0 + xkq * 4);
            v1 = *(const float4*)(Xg + k0 + (xkq + 2) * 4);
            wv = *(const float4*)(Wg + k0 + wkq * 4);
        }

        // ---- software-pipelined kk loop (prefetch next kk into regs) ----
        float4     a_c = *(const float4*)&Xb[tym << 2];
        ulonglong2 b_c = *(const ulonglong2*)&Wb[txn << 2];
#pragma unroll
        for (int kk = 0; kk < 16; kk++) {
            float4 a_n; ulonglong2 b_n;
            if (kk < 15) {
                a_n = *(const float4*)&Xb[(kk + 1) * 64 + (tym << 2)];
                b_n = *(const ulonglong2*)&Wb[(kk + 1) * 32 + (txn << 2)];
            }
            const u64 a0 = dup2(a_c.x), a1 = dup2(a_c.y);
            const u64 a2 = dup2(a_c.z), a3 = dup2(a_c.w);
            acc[0][0] = ffma2(a0, b_c.x, acc[0][0]); acc[0][1] = ffma2(a0, b_c.y, acc[0][1]);
            acc[1][0] = ffma2(a1, b_c.x, acc[1][0]); acc[1][1] = ffma2(a1, b_c.y, acc[1][1]);
            acc[2][0] = ffma2(a2, b_c.x, acc[2][0]); acc[2][1] = ffma2(a2, b_c.y, acc[2][1]);
            acc[3][0] = ffma2(a3, b_c.x, acc[3][0]); acc[3][1] = ffma2(a3, b_c.y, acc[3][1]);
            if (kk < 15) { a_c = a_n; b_c = b_n; }
        }

        if (pf) {
            float* Xn = Xs + ((c + 1) & 1) * 1024;
            float* Wn = Wt + ((c + 1) & 1) * 512;
            Xn[(xkq*4+0)*64 + xrow] = v0.x; Xn[(xkq*4+1)*64 + xrow] = v0.y;
            Xn[(xkq*4+2)*64 + xrow] = v0.z; Xn[(xkq*4+3)*64 + xrow] = v0.w;
            Xn[((xkq+2)*4+0)*64 + xrow] = v1.x; Xn[((xkq+2)*4+1)*64 + xrow] = v1.y;
            Xn[((xkq+2)*4+2)*64 + xrow] = v1.z; Xn[((xkq+2)*4+3)*64 + xrow] = v1.w;
            Wn[(wkq*4+0)*32 + wrow] = wv.x; Wn[(wkq*4+1)*32 + wrow] = wv.y;
            Wn[(wkq*4+2)*32 + wrow] = wv.z; Wn[(wkq*4+3)*32 + wrow] = wv.w;
        }
        __syncthreads();
    }

    // ---- epilogue ----
    const int n = n0 + txn * 4;
    float4 q0 = make_float4(0.f, 0.f, 0.f, 0.f), q1 = q0, q2 = q0, q3 = q0, q4 = q0;
    if (mode == 0) {
        q0 = *(const float4*)(p0 + n); q1 = *(const float4*)(p1 + n);
        q2 = *(const float4*)(p2 + n); q3 = *(const float4*)(p3 + n);
        q4 = *(const float4*)(p4 + n);
    } else if (mode == 2 || mode == 3) {
        q0 = *(const float4*)(p0 + n);
    }
    const float* bias = &q0.x;
    const float* gam  = &q1.x;
    const float* bet  = &q2.x;
    const float* mean = &q3.x;
    const float* var  = &q4.x;

#pragma unroll
    for (int r = 0; r < 4; r++) {
        float v[4];
        unpack2(acc[r][0], v[0], v[1]);
        unpack2(acc[r][1], v[2], v[3]);
#pragma unroll
        for (int c2 = 0; c2 < 4; c2++) {
            float v2 = v[c2];
            if (mode == 0) {
                v2 += bias[c2];
                v2 = gam[c2] * (v2 - mean[c2]) * rsqrtf(var[c2] + 1e-5f) + bet[c2];
                v2 = fmaxf(v2, 0.f);
            } else if (mode == 2) {
                v2 += bias[c2];
            } else if (mode == 3) {
                v2 = fmaxf(v2 + bias[c2], 0.f);
            }
            v[c2] = v2;
        }
        *(float4*)(Out + (size_t)(m0 + tym * 4 + r) * N + n) =
            make_float4(v[0], v[1], v[2], v[3]);
    }
}

// ============================================================
// Launch 1: three fused x-projections (H via BN+ReLU, A, C+bs1)
// grid (16 n-tiles, 8 m-tiles, 3 weights), 128 threads.
// ============================================================
__global__ __launch_bounds__(128)
void k_proj(const float* __restrict__ x,
            const float* __restrict__ W1, const float* __restrict__ b1,
            const float* __restrict__ gam, const float* __restrict__ bet,
            const float* __restrict__ mean, const float* __restrict__ var,
            const float* __restrict__ Wa, const float* __restrict__ Wb,
            const float* __restrict__ bs1)
{
    __shared__ __align__(16) float sm[3072];
    const int m0 = blockIdx.y * 64;
    const int n0 = blockIdx.x * 32;
    const int z  = blockIdx.z;
    if (z == 0)
        gemm_tile(x, W1, g_H, HIDD, INDIM, m0, n0, 0, b1, gam, bet, mean, var, sm);
    else if (z == 1)
        gemm_tile(x, Wa, g_A, HIDD, INDIM, m0, n0, 1,
                  nullptr, nullptr, nullptr, nullptr, nullptr, sm);
    else
        gemm_tile(x, Wb, g_C, HIDD, INDIM, m0, n0, 2,
                  bs1, nullptr, nullptr, nullptr, nullptr, sm);
}

// ============================================================
// Launch 2: blocks [0,136) = pairwise-similarity tiles (upper tri),
//           blocks [136,200) = H2 = relu(H @ W2^T + b2).
// 128 threads per block. sim: 32x32 pair tile, 2i x 4j micro-tile,
// double-buffered smem + kk register prefetch.
// ============================================================
__global__ __launch_bounds__(128)
void k_simh2(const float* __restrict__ W2, const float* __restrict__ b2,
             const float* __restrict__ ws2, const float* __restrict__ bs2p,
             float* __restrict__ out_sim)
{
    __shared__ __align__(16) float sm[4160];

    if (blockIdx.x >= 136) {
        const int idx = blockIdx.x - 136;          // 0..63
        const int m0 = (idx >> 3) * 64;            // 8 m-tiles
        const int n0 = (idx & 7) * 32;             // 8 n-tiles
        gemm_tile(g_H, W2, g_H2, HID2, HIDD, m0, n0, 3,
                  b2, nullptr, nullptr, nullptr, nullptr, sm);
        return;
    }

    // ---- similarity tile ----
    float* As = sm;          // 2 * 32 * 32
    float* Cs = sm + 2048;   // 2 * 32 * 32
    float* Ws = sm + 4096;   // 2 * 32

    // decode upper-triangle tile (bi <= bj) from linear block id
    int rb = blockIdx.x, bi = 0;
    while (rb >= 16 - bi) { rb -= 16 - bi; ++bi; }
    const int bj = bi + rb;
    const int i0 = bi * 32, j0 = bj * 32;

    const int t  = threadIdx.x;
    const int tx = t & 7;     // j quad (4 cols)
    const int ty = t >> 3;    // i pair (2 rows), 0..15

    const int lrow = t & 31;  // loader row
    const int lkq  = t >> 5;  // 0..3 (handles kq and kq+4)

    const float* Ag = g_A + (size_t)(i0 + lrow) * HIDD;
    const float* Cg = g_C + (size_t)(j0 + lrow) * HIDD;

    // ---- load chunk 0 ----
    {
        float4 a0 = *(const float4*)(Ag + lkq * 4);
        float4 a1 = *(const float4*)(Ag + (lkq + 4) * 4);
        float4 c0 = *(const float4*)(Cg + lkq * 4);
        float4 c1 = *(const float4*)(Cg + (lkq + 4) * 4);
        As[(lkq*4+0)*32 + lrow] = a0.x; As[(lkq*4+1)*32 + lrow] = a0.y;
        As[(lkq*4+2)*32 + lrow] = a0.z; As[(lkq*4+3)*32 + lrow] = a0.w;
        As[((lkq+4)*4+0)*32 + lrow] = a1.x; As[((lkq+4)*4+1)*32 + lrow] = a1.y;
        As[((lkq+4)*4+2)*32 + lrow] = a1.z; As[((lkq+4)*4+3)*32 + lrow] = a1.w;
        Cs[(lkq*4+0)*32 + lrow] = c0.x; Cs[(lkq*4+1)*32 + lrow] = c0.y;
        Cs[(lkq*4+2)*32 + lrow] = c0.z; Cs[(lkq*4+3)*32 + lrow] = c0.w;
        Cs[((lkq+4)*4+0)*32 + lrow] = c1.x; Cs[((lkq+4)*4+1)*32 + lrow] = c1.y;
        Cs[((lkq+4)*4+2)*32 + lrow] = c1.z; Cs[((lkq+4)*4+3)*32 + lrow] = c1.w;
        if (t < 8) *(float4*)&Ws[t * 4] = *(const float4*)(ws2 + t * 4);
    }
    __syncthreads();

    float acc[2][4];
#pragma unroll
    for (int r = 0; r < 2; r++)
#pragma unroll
        for (int c = 0; c < 4; c++) acc[r][c] = 0.f;

#pragma unroll 1
    for (int ch = 0; ch < 16; ++ch) {
        const float* Ab = As + (ch & 1) * 1024;
        const float* Cb = Cs + (ch & 1) * 1024;
        const float* Wb = Ws + (ch & 1) * 32;

        float4 a0, a1, c0, c1, wv;
        const bool pf = (ch + 1 < 16);
        if (pf) {
            const int k0 = (ch + 1) << 5;
            a0 = *(const float4*)(Ag + k0 + lkq * 4);
            a1 = *(const float4*)(Ag + k0 + (lkq + 4) * 4);
            c0 = *(const float4*)(Cg + k0 + lkq * 4);
            c1 = *(const float4*)(Cg + k0 + (lkq + 4) * 4);
            if (t < 8) wv = *(const float4*)(ws2 + k0 + t * 4);
        }

        // ---- software-pipelined kk loop ----
        float2 a_c = *(const float2*)&Ab[ty * 2];
        float4 c_c = *(const float4*)&Cb[tx * 4];
        float  w_c = Wb[0];
#pragma unroll
        for (int kk = 0; kk < 32; kk++) {
            float2 a_n; float4 c_n; float w_n;
            if (kk < 31) {
                a_n = *(const float2*)&Ab[(kk + 1) * 32 + ty * 2];
                c_n = *(const float4*)&Cb[(kk + 1) * 32 + tx * 4];
                w_n = Wb[kk + 1];
            }
            acc[0][0] += fmaxf(a_c.x + c_c.x, 0.f) * w_c;
            acc[0][1] += fmaxf(a_c.x + c_c.y, 0.f) * w_c;
            acc[0][2] += fmaxf(a_c.x + c_c.z, 0.f) * w_c;
            acc[0][3] += fmaxf(a_c.x + c_c.w, 0.f) * w_c;
            acc[1][0] += fmaxf(a_c.y + c_c.x, 0.f) * w_c;
            acc[1][1] += fmaxf(a_c.y + c_c.y, 0.f) * w_c;
            acc[1][2] += fmaxf(a_c.y + c_c.z, 0.f) * w_c;
            acc[1][3] += fmaxf(a_c.y + c_c.w, 0.f) * w_c;
            if (kk < 31) { a_c = a_n; c_c = c_n; w_c = w_n; }
        }

        if (pf) {
            float* An = As + ((ch + 1) & 1) * 1024;
            float* Cn = Cs + ((ch + 1) & 1) * 1024;
            An[(lkq*4+0)*32 + lrow] = a0.x; An[(lkq*4+1)*32 + lrow] = a0.y;
            An[(lkq*4+2)*32 + lrow] = a0.z; An[(lkq*4+3)*32 + lrow] = a0.w;
            An[((lkq+4)*4+0)*32 + lrow] = a1.x; An[((lkq+4)*4+1)*32 + lrow] = a1.y;
            An[((lkq+4)*4+2)*32 + lrow] = a1.z; An[((lkq+4)*4+3)*32 + lrow] = a1.w;
            Cn[(lkq*4+0)*32 + lrow] = c0.x; Cn[(lkq*4+1)*32 + lrow] = c0.y;
            Cn[(lkq*4+2)*32 + lrow] = c0.z; Cn[(lkq*4+3)*32 + lrow] = c0.w;
            Cn[((lkq+4)*4+0)*32 + lrow] = c1.x; Cn[((lkq+4)*4+1)*32 + lrow] = c1.y;
            Cn[((lkq+4)*4+2)*32 + lrow] = c1.z; Cn[((lkq+4)*4+3)*32 + lrow] = c1.w;
            if (t < 8) *(float4*)&Ws[((ch + 1) & 1) * 32 + t * 4] = wv;
        }
        __syncthreads();
    }

    const float bs2 = *bs2p;
#pragma unroll
    for (int r = 0; r < 2; r++) {
#pragma unroll
        for (int c = 0; c < 4; c++) {
            const int i = i0 + ty * 2 + r;
            const int j = j0 + tx * 4 + c;
            if (i < j) {
                const float s = 1.f / (1.f + __expf(-(acc[r][c] + bs2)));
                out_sim[(size_t)i * BATCH + j] = s;
                out_sim[(size_t)j * BATCH + i] = s;
            } else if (i == j) {
                out_sim[(size_t)i * BATCH + j] = 0.f;
            }
        }
    }
}

// ============================================================
// Launch 3: scores + softmax (reads g_H2), one warp per row.
// ============================================================
__global__ __launch_bounds__(128)
void k_scores(const float* __restrict__ W3, const float* __restrict__ b3,
              float* __restrict__ out_probs, float* __restrict__ out_scores)
{
    const int warp = threadIdx.x >> 5;
    const int lane = threadIdx.x & 31;
    const int row  = blockIdx.x * 4 + warp;
    const float* h = g_H2 + (size_t)row * HID2;

    float acc[PAT];
#pragma unroll
    for (int p = 0; p < PAT; p++) acc[p] = 0.f;

    for (int k = lane; k < HID2; k += 32) {
        const float hv = h[k];
#pragma unroll
        for (int p = 0; p < PAT; p++) acc[p] += hv * W3[p * HID2 + k];
    }
#pragma unroll
    for (int p = 0; p < PAT; p++) {
#pragma unroll
        for (int off = 16; off; off >>= 1)
            acc[p] += __shfl_xor_sync(0xFFFFFFFFu, acc[p], off);
    }
    if (lane == 0) {
        float s[PAT], e[PAT];
        float mx = -1e30f;
#pragma unroll
        for (int p = 0; p < PAT; p++) { s[p] = acc[p] + b3[p]; mx = fmaxf(mx, s[p]); }
        float sum = 0.f;
#pragma unroll
        for (int p = 0; p < PAT; p++) { e[p] = __expf(s[p] - mx); sum += e[p]; }
        const float inv = 1.f / sum;
#pragma unroll
        for (int p = 0; p < PAT; p++) {
            out_scores[row * PAT + p] = s[p];
            out_probs [row * PAT + p] = e[p] * inv;
        }
    }
}

// ============================================================
extern "C" void kernel_launch(void* const* d_in, const int* in_sizes, int n_in,
                              void* d_out, int out_size)
{
    const float* x    = (const float*)d_in[0];
    const float* W1   = (const float*)d_in[1];
    const float* b1   = (const float*)d_in[2];
    const float* gam  = (const float*)d_in[3];
    const float* bet  = (const float*)d_in[4];
    const float* mean = (const float*)d_in[5];
    const float* var  = (const float*)d_in[6];
    const float* W2   = (const float*)d_in[7];
    const float* b2   = (const float*)d_in[8];
    const float* W3   = (const float*)d_in[9];
    const float* b3   = (const float*)d_in[10];
    const float* Wa   = (const float*)d_in[11];
    const float* Wb   = (const float*)d_in[12];
    const float* bs1  = (const float*)d_in[13];
    const float* ws2  = (const float*)d_in[14];
    const float* bs2  = (const float*)d_in[15];

    float* out        = (float*)d_out;
    float* out_probs  = out;
    float* out_scores = out + BATCH * PAT;
    float* out_sim    = out + 2 * BATCH * PAT;

    // 1) H, A, C projections (384 CTAs)
    k_proj<<<dim3(16, 8, 3), 128>>>(x, W1, b1, gam, bet, mean, var, Wa, Wb, bs1);
    // 2) sim (136 CTAs) + H2 (64 CTAs) concurrently in one launch
    k_simh2<<<200, 128>>>(W2, b2, ws2, bs2, out_sim);
    // 3) scores + softmax
    k_scores<<<BATCH / 4, 128>>>(W3, b3, out_probs, out_scores);
}